// round 8
// baseline (speedup 1.0000x reference)
#include <cuda_runtime.h>
#include <cuda_bf16.h>

// One patch per thread; 16 amplitudes as 8 f32x2 with lane0 = amp m,
// lane1 = amp 15-m. R8: the qubit-0 fold and the Walsh trees are now ALSO
// packed, exploiting the complement symmetry:
//   pair (s, s+8) = (lane0 of reg s, lane1 of reg 7-s)
//   swapping regs 7-s makes SUM/ND/Cx lane-wise, with lane1 = -(pair 7-s)
//   for ND/Cx; the mask sign patterns under s -> 7-s absorb the flips:
//     E12 = lo+hi of (D0+D1+D2+D3)        E14 = lo-hi of (D0+D1-D2-D3)
//     E15 = lo+hi of ((D0+D3)-(D1+D2))    E7  = lo-hi of ((S0+S3)-(S1+S2))
//
// Algebra chain (validated R1-R7, rel_err ~1e-6):
//  * encoding diagonal after H^4, Psi via CSE tree
//  * RX butterflies qubits 1,2,3 packed
//  * qubit-0 RX + CNOT-ring Walsh masks folded analytically
//  * 1/16 scale on outputs

typedef unsigned long long u64;

__device__ __forceinline__ u64 pk2(float lo, float hi) {
    u64 r; asm("mov.b64 %0,{%1,%2};" : "=l"(r) : "f"(lo), "f"(hi)); return r;
}
__device__ __forceinline__ void unpk(u64 v, float& lo, float& hi) {
    asm("mov.b64 {%0,%1},%2;" : "=f"(lo), "=f"(hi) : "l"(v));
}
__device__ __forceinline__ u64 sw2(u64 v) {   // swap lanes
    float lo, hi; unpk(v, lo, hi); return pk2(hi, lo);
}
__device__ __forceinline__ u64 add2(u64 a, u64 b) {
    u64 d; asm("add.rn.f32x2 %0,%1,%2;" : "=l"(d) : "l"(a), "l"(b)); return d;
}
__device__ __forceinline__ u64 sub2(u64 a, u64 b) {
    u64 d; asm("sub.rn.f32x2 %0,%1,%2;" : "=l"(d) : "l"(a), "l"(b)); return d;
}
__device__ __forceinline__ u64 mul2(u64 a, u64 b) {
    u64 d; asm("mul.rn.f32x2 %0,%1,%2;" : "=l"(d) : "l"(a), "l"(b)); return d;
}
__device__ __forceinline__ u64 fma2(u64 a, u64 b, u64 c) {
    u64 d; asm("fma.rn.f32x2 %0,%1,%2,%3;" : "=l"(d) : "l"(a), "l"(b), "l"(c)); return d;
}

__global__ void __launch_bounds__(64)
qconv_kernel(const float* __restrict__ img,
             const float* __restrict__ wts,
             float* __restrict__ out,
             int npatch)
{
    int tid = blockIdx.x * blockDim.x + threadIdx.x;
    if (tid >= npatch) return;

    int b   = tid / 196;
    int rem = tid - b * 196;        // j*14 + k
    int j   = rem / 14;
    int k   = rem - j * 14;

    const float* base = img + (size_t)b * 784 + (size_t)(2 * j) * 28 + (size_t)(2 * k);
    float2 r0 = *reinterpret_cast<const float2*>(base);       // x0 x1
    float2 r1 = *reinterpret_cast<const float2*>(base + 28);  // x2 x3
    float x0 = r0.x, x1 = r0.y, x2 = r1.x, x3 = r1.y;

    const float HR = 0.3925f;       // 0.785/2
    float h0 = x0 * HR, h1 = x1 * HR, h2 = x2 * HR, h3 = x3 * HR;
    float p01 = h0 * x1, p02 = h0 * x2, p03 = h0 * x3;
    float p12 = h1 * x2, p13 = h1 * x3, p23 = h2 * x3;

    // single-qubit bases S
    float a01 = h0 + h1, b01 = h0 - h1;
    float a23 = h2 + h3, b23 = h2 - h3;
    float SA = a01 + a23, SB = a01 - a23;
    float SC = b01 + a23, SD = b01 - a23;
    float SE = a01 + b23, SF = a01 - b23;
    float SG = b01 + b23, SH = b01 - b23;

    // pair bases P
    float m_ = p12 + p13, n_ = p12 - p13;
    float t_pp = p01 - m_, t_mm = p01 + m_;
    float t_pm = p01 - n_, t_mp = p01 + n_;
    float u_ = p02 + p03, v_ = p02 - p03;
    float q_pp = u_ - p23, q_mm = u_ + p23;
    float q_pm = v_ + p23, q_mp = v_ - p23;

    float P0 = -(t_mm + q_mm);  // m=0: S=SA
    float P1 = -(t_mp + q_mp);  // m=1: S=SE
    float P2 = q_pm - t_pm;     // m=2: S=SF
    float P3 = q_pp - t_pp;     // m=3: S=SB
    float P4 = t_mm - q_mm;     // m=4: S=SC
    float P5 = t_mp - q_mp;     // m=5: S=SG
    float P6 = t_pm + q_pm;     // m=6: S=SH
    float P7 = t_pp + q_pp;     // m=7: S=SD

    float Sv[8] = { SA, SE, SF, SB, SC, SG, SH, SD };
    float Pv[8] = { P0, P1, P2, P3, P4, P5, P6, P7 };

    // packed amplitudes: lane0 = e^{i(P-S)}, lane1 = e^{i(P+S)}
    u64 AR[8], AI[8];
#pragma unroll
    for (int m = 0; m < 8; ++m) {
        float lo = Pv[m] - Sv[m];
        float hi = Pv[m] + Sv[m];
        float sl, cl, sh, ch;
        __sincosf(lo, &sl, &cl);
        __sincosf(hi, &sh, &ch);
        AR[m] = pk2(cl, ch);
        AI[m] = pk2(sl, sh);
    }

    // RX butterflies for qubits 1,2,3 (bits 4,2,1), valid in both lanes
#pragma unroll
    for (int q = 1; q < 4; ++q) {
        float sw, cw;
        __sincosf(__ldg(wts + q) * 0.5f, &sw, &cw);
        u64 cw2 = pk2(cw, cw), sw2v = pk2(sw, sw);
        int bit = 1 << (3 - q);
#pragma unroll
        for (int m = 0; m < 8; ++m) {
            if (m & bit) continue;
            int t = m | bit;
            u64 a0r = AR[m], a0i = AI[m];
            u64 a1r = AR[t], a1i = AI[t];
            AR[m] = fma2(cw2, a0r, mul2(sw2v, a1i));
            AI[m] = sub2(mul2(cw2, a0i), mul2(sw2v, a1r));
            AR[t] = fma2(cw2, a1r, mul2(sw2v, a0i));
            AI[t] = sub2(mul2(cw2, a1i), mul2(sw2v, a0r));
        }
    }

    // ---- packed qubit-0 fold over s = 0..3 (partner register 7-s) ----
    float s0, c0;
    __sincosf(__ldg(wts + 0), &s0, &c0);
    u64 c0p  = pk2(c0, c0);
    u64 s0p2 = pk2(2.0f * s0, 2.0f * s0);

    u64 SUMP[4], DIFP[4];
#pragma unroll
    for (int s = 0; s < 4; ++s) {
        int r = 7 - s;
        u64 ARsw = sw2(AR[r]);   // lanes: (amp s+8, amp 7-s)
        u64 AIsw = sw2(AI[r]);
        u64 NsP = fma2(AI[s], AI[s], mul2(AR[s], AR[s]));   // (N_s, N_{15-s})
        u64 NtP = fma2(AIsw,  AIsw,  mul2(ARsw,  ARsw));    // (N_{s+8}, N_{7-s})
        SUMP[s] = add2(NsP, NtP);                 // (SUM[s],  SUM[7-s])
        u64 NDP = sub2(NsP, NtP);                 // (Nd[s],  -Nd[7-s])
        u64 CxP = sub2(mul2(AR[s], AIsw), mul2(AI[s], ARsw)); // (Cx[s], -Cx[7-s])
        DIFP[s] = fma2(c0p, NDP, mul2(s0p2, CxP));            // (DIF[s], -DIF[7-s])
    }

    // ---- packed Walsh trees ----
    u64 t01 = add2(DIFP[0], DIFP[1]);
    u64 t23 = add2(DIFP[2], DIFP[3]);
    u64 U12 = add2(t01, t23);                       // E12 = lo+hi
    u64 U14 = sub2(t01, t23);                       // E14 = lo-hi
    u64 T15 = sub2(add2(DIFP[0], DIFP[3]), add2(DIFP[1], DIFP[2])); // E15 = lo+hi
    u64 U7  = sub2(add2(SUMP[0], SUMP[3]), add2(SUMP[1], SUMP[2])); // E7  = lo-hi

    float lo_, hi_;
    unpk(T15, lo_, hi_); float E15 = lo_ + hi_;
    unpk(U14, lo_, hi_); float E14 = lo_ - hi_;
    unpk(U12, lo_, hi_); float E12 = lo_ + hi_;
    unpk(U7,  lo_, hi_); float E7  = lo_ - hi_;

    const float SC16 = 0.0625f;
    // output (B,4,14,14), channels [Z3,Z2,Z1,Z0]
    float* o = out + (size_t)b * 784 + rem;
    o[0]   = E15 * SC16;   // Z3 (mask 15)
    o[196] = E14 * SC16;   // Z2 (mask 14)
    o[392] = E12 * SC16;   // Z1 (mask 12)
    o[588] = E7  * SC16;   // Z0 (mask 7)
}

extern "C" void kernel_launch(void* const* d_in, const int* in_sizes, int n_in,
                              void* d_out, int out_size) {
    const float* img = (const float*)d_in[0];
    const float* wts = (const float*)d_in[1];
    float* out = (float*)d_out;

    int B = in_sizes[0] / 784;
    int npatch = B * 196;

    int threads = 64;
    int blocks = (npatch + threads - 1) / threads;
    qconv_kernel<<<blocks, threads>>>(img, wts, out, npatch);
}

// round 9
// speedup vs baseline: 1.1037x; 1.1037x over previous
#include <cuda_runtime.h>
#include <cuda_bf16.h>

// One patch per thread; 16 amplitudes as 8 f32x2 (lane0 = amp m, lane1 = amp 15-m).
// R9 = R7 (best) + two changes:
//  1) tangent-form RX butterflies: a' = a0 + tan(w/2)*a1 (1 fma per output,
//     was 2 ops); the dropped cos(w/2) factors are deferred into the final
//     output scale (probabilities scale by (c1*c2*c3)^-2).
//  2) uniform trig (weights) hoisted into a 1-thread setup kernel writing a
//     __device__ global; worker threads just load 8 floats.
//
// Algebra chain (validated R1-R8, rel_err ~1e-6):
//  * encoding diagonal after H^4, Psi via CSE tree
//  * RX butterflies qubits 1,2,3 packed (tangent form)
//  * qubit-0 RX + CNOT-ring Walsh masks {7,12,14,15} folded analytically
//  * total scale 0.0625*(c1*c2*c3)^2 on outputs

typedef unsigned long long u64;

__device__ float g_params[8];
// [0]=cos(w0) [1]=2*sin(w0) [2]=tan(w1/2) [3]=tan(w2/2) [4]=tan(w3/2)
// [5]=0.0625*(c1*c2*c3)^2

__global__ void setup_kernel(const float* __restrict__ wts)
{
    float w0 = wts[0], w1 = wts[1], w2 = wts[2], w3 = wts[3];
    float s0, c0; __sincosf(w0, &s0, &c0);
    float s1, c1; __sincosf(w1 * 0.5f, &s1, &c1);
    float s2, c2; __sincosf(w2 * 0.5f, &s2, &c2);
    float s3, c3; __sincosf(w3 * 0.5f, &s3, &c3);
    g_params[0] = c0;
    g_params[1] = 2.0f * s0;
    g_params[2] = s1 / c1;
    g_params[3] = s2 / c2;
    g_params[4] = s3 / c3;
    float cc = c1 * c2 * c3;
    g_params[5] = 0.0625f * cc * cc;
}

__device__ __forceinline__ u64 pk2(float lo, float hi) {
    u64 r; asm("mov.b64 %0,{%1,%2};" : "=l"(r) : "f"(lo), "f"(hi)); return r;
}
__device__ __forceinline__ void unpk(u64 v, float& lo, float& hi) {
    asm("mov.b64 {%0,%1},%2;" : "=f"(lo), "=f"(hi) : "l"(v));
}
__device__ __forceinline__ u64 fma2(u64 a, u64 b, u64 c) {
    u64 d; asm("fma.rn.f32x2 %0,%1,%2,%3;" : "=l"(d) : "l"(a), "l"(b), "l"(c)); return d;
}

__global__ void __launch_bounds__(64)
qconv_kernel(const float* __restrict__ img,
             float* __restrict__ out,
             int npatch)
{
    int tid = blockIdx.x * blockDim.x + threadIdx.x;
    if (tid >= npatch) return;

    int b   = tid / 196;
    int rem = tid - b * 196;        // j*14 + k
    int j   = rem / 14;
    int k   = rem - j * 14;

    const float* base = img + (size_t)b * 784 + (size_t)(2 * j) * 28 + (size_t)(2 * k);
    float2 r0 = *reinterpret_cast<const float2*>(base);       // x0 x1
    float2 r1 = *reinterpret_cast<const float2*>(base + 28);  // x2 x3
    float x0 = r0.x, x1 = r0.y, x2 = r1.x, x3 = r1.y;

    const float HR = 0.3925f;       // 0.785/2
    float h0 = x0 * HR, h1 = x1 * HR, h2 = x2 * HR, h3 = x3 * HR;
    float p01 = h0 * x1, p02 = h0 * x2, p03 = h0 * x3;
    float p12 = h1 * x2, p13 = h1 * x3, p23 = h2 * x3;

    // single-qubit bases S
    float a01 = h0 + h1, b01 = h0 - h1;
    float a23 = h2 + h3, b23 = h2 - h3;
    float SA = a01 + a23, SB = a01 - a23;
    float SC = b01 + a23, SD = b01 - a23;
    float SE = a01 + b23, SF = a01 - b23;
    float SG = b01 + b23, SH = b01 - b23;

    // pair bases P
    float m_ = p12 + p13, n_ = p12 - p13;
    float t_pp = p01 - m_, t_mm = p01 + m_;
    float t_pm = p01 - n_, t_mp = p01 + n_;
    float u_ = p02 + p03, v_ = p02 - p03;
    float q_pp = u_ - p23, q_mm = u_ + p23;
    float q_pm = v_ + p23, q_mp = v_ - p23;

    float P0 = -(t_mm + q_mm);  // m=0: S=SA
    float P1 = -(t_mp + q_mp);  // m=1: S=SE
    float P2 = q_pm - t_pm;     // m=2: S=SF
    float P3 = q_pp - t_pp;     // m=3: S=SB
    float P4 = t_mm - q_mm;     // m=4: S=SC
    float P5 = t_mp - q_mp;     // m=5: S=SG
    float P6 = t_pm + q_pm;     // m=6: S=SH
    float P7 = t_pp + q_pp;     // m=7: S=SD

    float Sv[8] = { SA, SE, SF, SB, SC, SG, SH, SD };
    float Pv[8] = { P0, P1, P2, P3, P4, P5, P6, P7 };

    // packed amplitudes: lane0 = e^{i(P-S)}, lane1 = e^{i(P+S)}
    u64 AR[8], AI[8];
#pragma unroll
    for (int m = 0; m < 8; ++m) {
        float lo = Pv[m] - Sv[m];
        float hi = Pv[m] + Sv[m];
        float sl, cl, sh, ch;
        __sincosf(lo, &sl, &cl);
        __sincosf(hi, &sh, &ch);
        AR[m] = pk2(cl, ch);
        AI[m] = pk2(sl, sh);
    }

    // uniform params (tiny, L1/L2-resident)
    float c0  = g_params[0];
    float s02 = g_params[1];
    float tw1 = g_params[2];
    float tw2 = g_params[3];
    float tw3 = g_params[4];
    float SCL = g_params[5];

    // RX butterflies qubits 1,2,3 (bits 4,2,1), tangent form: 1 fma per output.
    float twv[3] = { tw1, tw2, tw3 };
#pragma unroll
    for (int q = 0; q < 3; ++q) {
        float tw = twv[q];
        u64 tw2p = pk2(tw, tw), ntw2p = pk2(-tw, -tw);
        int bit = 4 >> q;               // 4, 2, 1
#pragma unroll
        for (int m = 0; m < 8; ++m) {
            if (m & bit) continue;
            int t = m | bit;
            u64 a0r = AR[m], a0i = AI[m];
            u64 a1r = AR[t], a1i = AI[t];
            AR[m] = fma2(tw2p,  a1i, a0r);   // a0r + tw*a1i
            AI[m] = fma2(ntw2p, a1r, a0i);   // a0i - tw*a1r
            AR[t] = fma2(tw2p,  a0i, a1r);   // a1r + tw*a0i
            AI[t] = fma2(ntw2p, a0r, a1i);   // a1i - tw*a0r
        }
    }

    // qubit-0 fold (scalar, as in R7): pair (s, s+8) = (lane0 reg s, lane1 reg 7-s)
    float SUM[8], DIF[8];
#pragma unroll
    for (int s = 0; s < 4; ++s) {
        int r7 = 7 - s;
        float arl, arh, ail, aih;       // reg s
        float brl, brh, bil, bih;       // reg 7-s
        unpk(AR[s],  arl, arh);
        unpk(AI[s],  ail, aih);
        unpk(AR[r7], brl, brh);
        unpk(AI[r7], bil, bih);

        {   // pair s: a_s = (arl, ail), a_{s+8} = (brh, bih)
            float Ns = arl * arl + ail * ail;
            float Nt = brh * brh + bih * bih;
            float Cx = arl * bih - ail * brh;
            SUM[s] = Ns + Nt;
            DIF[s] = c0 * (Ns - Nt) + s02 * Cx;
        }
        {   // pair 7-s: a_{7-s} = (brl, bil), a_{15-s} = (arh, aih)
            float Ns = brl * brl + bil * bil;
            float Nt = arh * arh + aih * aih;
            float Cx = brl * aih - bil * arh;
            SUM[r7] = Ns + Nt;
            DIF[r7] = c0 * (Ns - Nt) + s02 * Cx;
        }
    }

    // Walsh trees over s = 4*b1 + 2*b2 + b3
    float d0 = DIF[0] - DIF[1], d1 = DIF[2] - DIF[3];
    float d2 = DIF[4] - DIF[5], d3 = DIF[6] - DIF[7];
    float e0 = DIF[0] + DIF[1], e1 = DIF[2] + DIF[3];
    float e2 = DIF[4] + DIF[5], e3 = DIF[6] + DIF[7];

    float E15 = (d0 - d1) - (d2 - d3);
    float E14 = (e0 - e1) - (e2 - e3);
    float E12 = (e0 + e1) - (e2 + e3);

    float w0_ = SUM[0] - SUM[1], w1_ = SUM[2] - SUM[3];
    float w2_ = SUM[4] - SUM[5], w3_ = SUM[6] - SUM[7];
    float E7 = (w0_ - w1_) - (w2_ - w3_);

    // output (B,4,14,14), channels [Z3,Z2,Z1,Z0]; SCL = 0.0625*(c1c2c3)^2
    float* o = out + (size_t)b * 784 + rem;
    o[0]   = E15 * SCL;   // Z3 (mask 15)
    o[196] = E14 * SCL;   // Z2 (mask 14)
    o[392] = E12 * SCL;   // Z1 (mask 12)
    o[588] = E7  * SCL;   // Z0 (mask 7)
}

extern "C" void kernel_launch(void* const* d_in, const int* in_sizes, int n_in,
                              void* d_out, int out_size) {
    const float* img = (const float*)d_in[0];
    const float* wts = (const float*)d_in[1];
    float* out = (float*)d_out;

    int B = in_sizes[0] / 784;
    int npatch = B * 196;

    setup_kernel<<<1, 1>>>(wts);

    int threads = 64;
    int blocks = (npatch + threads - 1) / threads;
    qconv_kernel<<<blocks, threads>>>(img, out, npatch);
}